// round 1
// baseline (speedup 1.0000x reference)
#include <cuda_runtime.h>
#include <cuda_bf16.h>
#include <math.h>

#define NTOK 4096
#define DIM  1024
#define NEXP 8
#define TM   64
#define TN   64
#define KB   16
#define MAX_TILES (NTOK / TM + NEXP)   // 72 worst case

// ---------------- device scratch (no allocations allowed) ----------------
__device__ float g_weight[NTOK];
__device__ int   g_expert[NTOK];
__device__ int   g_counts[NEXP];
__device__ int   g_fill[NEXP];
__device__ int   g_offsets[NEXP + 1];
__device__ int   g_sorted[NTOK];
__device__ int2  g_tiles[MAX_TILES];
__device__ int   g_num_tiles;

// ---------------- kernel 0: reset counters ----------------
__global__ void k_init() {
    int t = threadIdx.x;
    if (t < NEXP) { g_counts[t] = 0; g_fill[t] = 0; }
}

// ---------------- kernel 1: router (1 warp per token) ----------------
__global__ void k_router(const float* __restrict__ x,
                         const float* __restrict__ rw,
                         const float* __restrict__ rb) {
    int warp = (blockIdx.x * blockDim.x + threadIdx.x) >> 5;
    int lane = threadIdx.x & 31;
    if (warp >= NTOK) return;

    const float* xr = x + (size_t)warp * DIM;
    float acc[NEXP];
#pragma unroll
    for (int e = 0; e < NEXP; e++) acc[e] = 0.f;

    for (int d = lane; d < DIM; d += 32) {
        float xv = xr[d];
#pragma unroll
        for (int e = 0; e < NEXP; e++) acc[e] += xv * rw[e * DIM + d];
    }
#pragma unroll
    for (int e = 0; e < NEXP; e++) {
#pragma unroll
        for (int o = 16; o > 0; o >>= 1)
            acc[e] += __shfl_xor_sync(0xFFFFFFFFu, acc[e], o);
    }
    if (lane == 0) {
        float best = -1e30f; int bi = 0;
#pragma unroll
        for (int e = 0; e < NEXP; e++) {
            float l = acc[e] + rb[e];
            if (l > best) { best = l; bi = e; }
        }
        float s = 0.f;
#pragma unroll
        for (int e = 0; e < NEXP; e++) s += __expf(acc[e] + rb[e] - best) * 0.f + expf(acc[e] + rb[e] - best);
        g_weight[warp] = 1.f / s;
        g_expert[warp] = bi;
        atomicAdd(&g_counts[bi], 1);
    }
}

// ---------------- kernel 2: scan (serial, E=8 — trivial) ----------------
__global__ void k_scan() {
    if (threadIdx.x == 0 && blockIdx.x == 0) {
        int off = 0, nt = 0;
        for (int e = 0; e < NEXP; e++) {
            g_offsets[e] = off;
            int c = g_counts[e];
            for (int s = 0; s < c; s += TM) g_tiles[nt++] = make_int2(e, off + s);
            off += c;
        }
        g_offsets[NEXP] = off;
        g_num_tiles = nt;
    }
}

// ---------------- kernel 3: scatter tokens into expert groups ----------------
__global__ void k_scatter() {
    int t = blockIdx.x * blockDim.x + threadIdx.x;
    if (t >= NTOK) return;
    int e = g_expert[t];
    int pos = g_offsets[e] + atomicAdd(&g_fill[e], 1);
    g_sorted[pos] = t;
}

// ---------------- kernel 4: grouped GEMM, 64x64 tile, 4x4 micro-tile ----------------
__global__ void __launch_bounds__(256) k_gemm(const float* __restrict__ x,
                                              const float* __restrict__ ew,
                                              const float* __restrict__ eb,
                                              float* __restrict__ out) {
    int tile = blockIdx.y;
    if (tile >= g_num_tiles) return;
    int2 td   = g_tiles[tile];
    int  e    = td.x;
    int  row0 = td.y;
    int  segend = g_offsets[e + 1];

    __shared__ float As[KB][TM];   // transposed: As[k][m]
    __shared__ float Bs[KB][TN];   // transposed: Bs[k][n]
    __shared__ int   s_tok[TM];
    __shared__ float s_w[TM];

    int tid = threadIdx.x;
    if (tid < TM) {
        int r = row0 + tid;
        int tok = (r < segend) ? g_sorted[r] : -1;
        s_tok[tid] = tok;
        s_w[tid]   = (tok >= 0) ? g_weight[tok] : 0.f;
    }
    __syncthreads();

    int n0 = blockIdx.x * TN;
    const float* wbase = ew + (size_t)e * DIM * DIM;

    // gmem->smem mapping: each thread loads one float4 of A and one of B
    int lm = tid >> 2;        // row 0..63
    int kv = tid & 3;         // float4 index within KB
    int tokm = s_tok[lm];
    const float* xrow = x + (size_t)((tokm < 0) ? 0 : tokm) * DIM;
    const float* wrow = wbase + (size_t)(n0 + lm) * DIM;

    int tx = tid & 15;        // n micro-tile
    int ty = tid >> 4;        // m micro-tile

    float acc[4][4];
#pragma unroll
    for (int i = 0; i < 4; i++)
#pragma unroll
        for (int j = 0; j < 4; j++) acc[i][j] = 0.f;

    for (int k0 = 0; k0 < DIM; k0 += KB) {
        float4 av = *(const float4*)(xrow + k0 + kv * 4);
        float4 bv = *(const float4*)(wrow + k0 + kv * 4);
        __syncthreads();   // previous iteration's reads done
        As[kv * 4 + 0][lm] = av.x;
        As[kv * 4 + 1][lm] = av.y;
        As[kv * 4 + 2][lm] = av.z;
        As[kv * 4 + 3][lm] = av.w;
        Bs[kv * 4 + 0][lm] = bv.x;
        Bs[kv * 4 + 1][lm] = bv.y;
        Bs[kv * 4 + 2][lm] = bv.z;
        Bs[kv * 4 + 3][lm] = bv.w;
        __syncthreads();
#pragma unroll
        for (int k = 0; k < KB; k++) {
            float4 a4 = *(const float4*)&As[k][ty * 4];
            float4 b4 = *(const float4*)&Bs[k][tx * 4];
            acc[0][0] += a4.x * b4.x; acc[0][1] += a4.x * b4.y;
            acc[0][2] += a4.x * b4.z; acc[0][3] += a4.x * b4.w;
            acc[1][0] += a4.y * b4.x; acc[1][1] += a4.y * b4.y;
            acc[1][2] += a4.y * b4.z; acc[1][3] += a4.y * b4.w;
            acc[2][0] += a4.z * b4.x; acc[2][1] += a4.z * b4.y;
            acc[2][2] += a4.z * b4.z; acc[2][3] += a4.z * b4.w;
            acc[3][0] += a4.w * b4.x; acc[3][1] += a4.w * b4.y;
            acc[3][2] += a4.w * b4.z; acc[3][3] += a4.w * b4.w;
        }
    }

    // epilogue: out[tok][n] = (acc + bias[n]) * weight[tok]
    float4 bias = *(const float4*)(eb + (size_t)e * DIM + n0 + tx * 4);
#pragma unroll
    for (int i = 0; i < 4; i++) {
        int m = ty * 4 + i;
        int tok = s_tok[m];
        if (tok < 0) continue;
        float w = s_w[m];
        float4 r;
        r.x = (acc[i][0] + bias.x) * w;
        r.y = (acc[i][1] + bias.y) * w;
        r.z = (acc[i][2] + bias.z) * w;
        r.w = (acc[i][3] + bias.w) * w;
        *(float4*)(out + (size_t)tok * DIM + n0 + tx * 4) = r;
    }
}

// ---------------- launch ----------------
extern "C" void kernel_launch(void* const* d_in, const int* in_sizes, int n_in,
                              void* d_out, int out_size) {
    const float* x   = (const float*)d_in[0];   // [2,2048,1024]
    const float* rw  = (const float*)d_in[1];   // [8,1024]
    const float* rb  = (const float*)d_in[2];   // [8]
    const float* ew  = (const float*)d_in[3];   // [8,1024,1024]
    const float* eb  = (const float*)d_in[4];   // [8,1024]
    float* out = (float*)d_out;                 // [2,2048,1024]

    k_init<<<1, 32>>>();
    k_router<<<(NTOK * 32) / 256, 256>>>(x, rw, rb);
    k_scan<<<1, 32>>>();
    k_scatter<<<NTOK / 256, 256>>>();
    dim3 grid(DIM / TN, MAX_TILES);
    k_gemm<<<grid, 256>>>(x, ew, eb, out);
}

// round 3
// speedup vs baseline: 3.6156x; 3.6156x over previous
#include <cuda_runtime.h>
#include <cuda_bf16.h>
#include <math.h>
#include <stdint.h>

#define NTOK 4096
#define DIM  1024
#define NEXP 8
#define TM   128
#define TN   128
#define KC   32                      // K elems per pipeline chunk
#define NCH  (DIM / KC)              // 32
#define MAX_TILES (NTOK / TM + NEXP) // 40

// padded SMEM row: 32 bf16 data + 8 pad = 40 elems = 80 bytes
#define SROW 80
#define MAT_BYTES   (128 * SROW)         // 10240
#define STAGE_BYTES (4 * MAT_BYTES)      // 40960
#define NSTAGE 3
#define SMEM_BYTES  (NSTAGE * STAGE_BYTES)

// ---------------- device scratch ----------------
__device__ float g_weight[NTOK];
__device__ int   g_expert[NTOK];
__device__ int   g_counts[NEXP];
__device__ int   g_fill[NEXP];
__device__ int   g_offsets[NEXP + 1];
__device__ int   g_sorted[NTOK];
__device__ int2  g_tiles[MAX_TILES];
__device__ int   g_num_tiles;
__device__ __nv_bfloat16 g_xhi[(NTOK + TM) * DIM];
__device__ __nv_bfloat16 g_xlo[(NTOK + TM) * DIM];
__device__ __nv_bfloat16 g_whi[NEXP * DIM * DIM];
__device__ __nv_bfloat16 g_wlo[NEXP * DIM * DIM];

// ---------------- PTX helpers (base compute_103 only!) ----------------
__device__ __forceinline__ uint32_t smem_u32(const void* p) {
    uint32_t a;
    asm("{ .reg .u64 t; cvta.to.shared.u64 t, %1; cvt.u32.u64 %0, t; }" : "=r"(a) : "l"(p));
    return a;
}
#define CP_ASYNC16(dst, src) \
    asm volatile("cp.async.cg.shared.global [%0], [%1], 16;" :: "r"(dst), "l"(src) : "memory")
#define CP_COMMIT() asm volatile("cp.async.commit_group;" ::: "memory")
#define CP_WAIT(n)  asm volatile("cp.async.wait_group %0;" :: "n"(n) : "memory")

#define LDSM_X4(r0, r1, r2, r3, addr) \
    asm volatile("ldmatrix.sync.aligned.m8n8.x4.shared.b16 {%0,%1,%2,%3}, [%4];" \
                 : "=r"(r0), "=r"(r1), "=r"(r2), "=r"(r3) : "r"(addr))

#define MMA_BF16(c, a, b) \
    asm volatile("mma.sync.aligned.m16n8k16.row.col.f32.bf16.bf16.f32 " \
                 "{%0,%1,%2,%3}, {%4,%5,%6,%7}, {%8,%9}, {%0,%1,%2,%3};" \
                 : "+f"((c)[0]), "+f"((c)[1]), "+f"((c)[2]), "+f"((c)[3]) \
                 : "r"((a)[0]), "r"((a)[1]), "r"((a)[2]), "r"((a)[3]), \
                   "r"((b)[0]), "r"((b)[1]))

// ---------------- small kernels ----------------
__global__ void k_init() {
    int t = threadIdx.x;
    if (t < NEXP) { g_counts[t] = 0; g_fill[t] = 0; }
}

__global__ void k_router(const float* __restrict__ x,
                         const float* __restrict__ rw,
                         const float* __restrict__ rb) {
    int warp = (blockIdx.x * blockDim.x + threadIdx.x) >> 5;
    int lane = threadIdx.x & 31;
    if (warp >= NTOK) return;
    const float* xr = x + (size_t)warp * DIM;
    float acc[NEXP];
#pragma unroll
    for (int e = 0; e < NEXP; e++) acc[e] = 0.f;
    for (int d = lane; d < DIM; d += 32) {
        float xv = xr[d];
#pragma unroll
        for (int e = 0; e < NEXP; e++) acc[e] += xv * rw[e * DIM + d];
    }
#pragma unroll
    for (int e = 0; e < NEXP; e++)
#pragma unroll
        for (int o = 16; o > 0; o >>= 1)
            acc[e] += __shfl_xor_sync(0xFFFFFFFFu, acc[e], o);
    if (lane == 0) {
        float best = -1e30f; int bi = 0;
#pragma unroll
        for (int e = 0; e < NEXP; e++) {
            float l = acc[e] + rb[e];
            if (l > best) { best = l; bi = e; }
        }
        float s = 0.f;
#pragma unroll
        for (int e = 0; e < NEXP; e++) s += expf(acc[e] + rb[e] - best);
        g_weight[warp] = 1.f / s;
        g_expert[warp] = bi;
        atomicAdd(&g_counts[bi], 1);
    }
}

__global__ void k_scan() {
    if (threadIdx.x == 0 && blockIdx.x == 0) {
        int off = 0, nt = 0;
        for (int e = 0; e < NEXP; e++) {
            g_offsets[e] = off;
            int c = g_counts[e];
            for (int s = 0; s < c; s += TM) g_tiles[nt++] = make_int2(e, off + s);
            off += c;
        }
        g_offsets[NEXP] = off;
        g_num_tiles = nt;
    }
}

__global__ void k_scatter() {
    int t = blockIdx.x * blockDim.x + threadIdx.x;
    if (t >= NTOK) return;
    int e = g_expert[t];
    int pos = g_offsets[e] + atomicAdd(&g_fill[e], 1);
    g_sorted[pos] = t;
}

__global__ void k_prep_x(const float* __restrict__ x) {
    int p = blockIdx.x;
    int tok = g_sorted[p];
    float4 v = ((const float4*)(x + (size_t)tok * DIM))[threadIdx.x];
    union { __nv_bfloat16 h[4]; uint2 u; } hi, lo;
    float f[4] = {v.x, v.y, v.z, v.w};
#pragma unroll
    for (int j = 0; j < 4; j++) {
        hi.h[j] = __float2bfloat16(f[j]);
        lo.h[j] = __float2bfloat16(f[j] - __bfloat162float(hi.h[j]));
    }
    ((uint2*)(g_xhi + (size_t)p * DIM))[threadIdx.x] = hi.u;
    ((uint2*)(g_xlo + (size_t)p * DIM))[threadIdx.x] = lo.u;
}

__global__ void k_prep_w(const float* __restrict__ ew) {
    size_t i4 = (size_t)blockIdx.x * blockDim.x + threadIdx.x;
    float4 v = ((const float4*)ew)[i4];
    union { __nv_bfloat16 h[4]; uint2 u; } hi, lo;
    float f[4] = {v.x, v.y, v.z, v.w};
#pragma unroll
    for (int j = 0; j < 4; j++) {
        hi.h[j] = __float2bfloat16(f[j]);
        lo.h[j] = __float2bfloat16(f[j] - __bfloat162float(hi.h[j]));
    }
    ((uint2*)g_whi)[i4] = hi.u;
    ((uint2*)g_wlo)[i4] = lo.u;
}

// ---------------- mma.sync grouped GEMM ----------------
__global__ void __launch_bounds__(256, 1) k_gemm(const float* __restrict__ eb,
                                                 float* __restrict__ out) {
    int tile = blockIdx.y;
    if (tile >= g_num_tiles) return;
    extern __shared__ char smem[];
    uint32_t sb = smem_u32(smem);
    __shared__ int   s_tok[TM];
    __shared__ float s_w[TM];

    int tid = threadIdx.x;
    int wid = tid >> 5;
    int lane = tid & 31;
    int warp_m = wid & 3;    // 32-row slab
    int warp_n = wid >> 2;   // 64-col slab

    int2 td = g_tiles[tile];
    int e = td.x, row0 = td.y;
    int segend = g_offsets[e + 1];
    int n0 = blockIdx.x * TN;

    if (tid < TM) {
        int r = row0 + tid;
        int tok = (r < segend) ? g_sorted[r] : -1;
        s_tok[tid] = tok;
        s_w[tid]   = (tok >= 0) ? g_weight[tok] : 0.f;
    }

    // per-thread gmem base rows for loads (8 x 16B per chunk)
    const __nv_bfloat16* srcbase[4];
    {
        // idx = i*256+tid; mat = idx>>9; w = idx&511; row = w>>2; seg = w&3
        // we precompute row-ptrs per i below instead
    }

    // per-thread ldmatrix lane offsets (bytes within a matrix)
    uint32_t aoff = (uint32_t)((warp_m * 32 + (lane & 15)) * SROW + (lane >> 4) * 16);
    uint32_t boff = (uint32_t)((warp_n * 64 + ((lane >> 4) << 3) + (lane & 7)) * SROW
                               + ((lane >> 3) & 1) * 16);

    float c[2][8][4];
#pragma unroll
    for (int mt = 0; mt < 2; mt++)
#pragma unroll
        for (int nt = 0; nt < 8; nt++)
#pragma unroll
            for (int j = 0; j < 4; j++) c[mt][nt][j] = 0.f;

    auto issue = [&](int ch, int st) {
        int k0 = ch * KC;
        uint32_t stbase = sb + st * STAGE_BYTES;
#pragma unroll
        for (int i = 0; i < 8; i++) {
            int idx = i * 256 + tid;
            int mat = idx >> 9;
            int w   = idx & 511;
            int row = w >> 2;
            int seg = w & 3;
            uint32_t dst = stbase + mat * MAT_BYTES + row * SROW + seg * 16;
            const __nv_bfloat16* src;
            if (mat == 0)      src = g_xhi + (size_t)(row0 + row) * DIM + k0 + seg * 8;
            else if (mat == 1) src = g_xlo + (size_t)(row0 + row) * DIM + k0 + seg * 8;
            else if (mat == 2) src = g_whi + (size_t)(e * DIM + n0 + row) * DIM + k0 + seg * 8;
            else               src = g_wlo + (size_t)(e * DIM + n0 + row) * DIM + k0 + seg * 8;
            CP_ASYNC16(dst, src);
        }
        CP_COMMIT();
    };

    issue(0, 0); issue(1, 1); issue(2, 2);

    for (int ch = 0; ch < NCH; ch++) {
        int st = ch % NSTAGE;
        CP_WAIT(2);
        __syncthreads();

        uint32_t sA = sb + st * STAGE_BYTES;
        uint32_t sB = sA + 2 * MAT_BYTES;
#pragma unroll
        for (int ks = 0; ks < 2; ks++) {
            uint32_t kb = ks * 32;           // 16 elems * 2B
            uint32_t ah[2][4], al[2][4], bh[8][2], bl[8][2];
#pragma unroll
            for (int mt = 0; mt < 2; mt++) {
                uint32_t a = sA + mt * (16 * SROW) + aoff + kb;
                LDSM_X4(ah[mt][0], ah[mt][1], ah[mt][2], ah[mt][3], a);
                LDSM_X4(al[mt][0], al[mt][1], al[mt][2], al[mt][3], a + MAT_BYTES);
            }
#pragma unroll
            for (int p = 0; p < 4; p++) {
                uint32_t b = sB + p * (16 * SROW) + boff + kb;
                LDSM_X4(bh[p * 2][0], bh[p * 2][1], bh[p * 2 + 1][0], bh[p * 2 + 1][1], b);
                LDSM_X4(bl[p * 2][0], bl[p * 2][1], bl[p * 2 + 1][0], bl[p * 2 + 1][1], b + MAT_BYTES);
            }
#pragma unroll
            for (int mt = 0; mt < 2; mt++)
#pragma unroll
                for (int nt = 0; nt < 8; nt++) {
                    MMA_BF16(c[mt][nt], ah[mt], bh[nt]);
                    MMA_BF16(c[mt][nt], ah[mt], bl[nt]);
                    MMA_BF16(c[mt][nt], al[mt], bh[nt]);
                }
        }
        __syncthreads();
        if (ch + NSTAGE < NCH) issue(ch + NSTAGE, st);
        else CP_COMMIT();   // keep group accounting uniform
    }

    // ---------------- epilogue ----------------
    int ncol_base = n0 + warp_n * 64 + (lane & 3) * 2;
#pragma unroll
    for (int mt = 0; mt < 2; mt++) {
#pragma unroll
        for (int half = 0; half < 2; half++) {
            int rl = warp_m * 32 + mt * 16 + (lane >> 2) + half * 8;
            int tok = s_tok[rl];
            if (tok < 0) continue;
            float wt = s_w[rl];
            float* orow = out + (size_t)tok * DIM;
#pragma unroll
            for (int nt = 0; nt < 8; nt++) {
                int nc = ncol_base + nt * 8;
                float b0 = eb[(size_t)e * DIM + nc];
                float b1 = eb[(size_t)e * DIM + nc + 1];
                float2 r2;
                r2.x = (c[mt][nt][half * 2 + 0] + b0) * wt;
                r2.y = (c[mt][nt][half * 2 + 1] + b1) * wt;
                *(float2*)(orow + nc) = r2;
            }
        }
    }
}

// ---------------- launch ----------------
extern "C" void kernel_launch(void* const* d_in, const int* in_sizes, int n_in,
                              void* d_out, int out_size) {
    const float* x  = (const float*)d_in[0];
    const float* rw = (const float*)d_in[1];
    const float* rb = (const float*)d_in[2];
    const float* ew = (const float*)d_in[3];
    const float* eb = (const float*)d_in[4];
    float* out = (float*)d_out;

    cudaFuncSetAttribute(k_gemm, cudaFuncAttributeMaxDynamicSharedMemorySize, SMEM_BYTES);

    k_init<<<1, 32>>>();
    k_router<<<(NTOK * 32) / 256, 256>>>(x, rw, rb);
    k_scan<<<1, 32>>>();
    k_scatter<<<NTOK / 256, 256>>>();
    k_prep_x<<<NTOK, 256>>>(x);
    k_prep_w<<<(NEXP * DIM * DIM) / (256 * 4), 256>>>(ew);
    dim3 grid(DIM / TN, MAX_TILES);
    k_gemm<<<grid, 256, SMEM_BYTES>>>(eb, out);
}

// round 4
// speedup vs baseline: 4.0942x; 1.1324x over previous
#include <cuda_runtime.h>
#include <cuda_bf16.h>
#include <math.h>
#include <stdint.h>

#define NTOK 4096
#define DIM  1024
#define NEXP 8
#define TM   128
#define TN   128
#define KC   32                      // K elems per pipeline chunk
#define NCH  (DIM / KC)              // 32
#define MAX_TILES (NTOK / TM + NEXP) // 40

// padded SMEM row: 32 bf16 data + 8 pad = 40 elems = 80 bytes
#define SROW 80
#define MAT_BYTES   (128 * SROW)         // 10240
#define STAGE_BYTES (4 * MAT_BYTES)      // 40960
#define NSTAGE 2
#define SMEM_BYTES  (NSTAGE * STAGE_BYTES)   // 81920

#define GEMM_CTAS (2 * 148)

// ---------------- device scratch ----------------
__device__ float g_weight[NTOK];
__device__ int   g_expert[NTOK];
__device__ int   g_counts[NEXP];
__device__ int   g_fill[NEXP];
__device__ int   g_offsets[NEXP + 1];
__device__ int   g_sorted[NTOK];
__device__ int2  g_tiles[MAX_TILES];
__device__ int   g_num_tiles;
__device__ int   g_ticket;
__device__ __nv_bfloat16 g_xhi[(NTOK + TM) * DIM];
__device__ __nv_bfloat16 g_xlo[(NTOK + TM) * DIM];
__device__ __nv_bfloat16 g_whi[NEXP * DIM * DIM];
__device__ __nv_bfloat16 g_wlo[NEXP * DIM * DIM];

// ---------------- PTX helpers (base compute_103 only) ----------------
__device__ __forceinline__ uint32_t smem_u32(const void* p) {
    uint32_t a;
    asm("{ .reg .u64 t; cvta.to.shared.u64 t, %1; cvt.u32.u64 %0, t; }" : "=r"(a) : "l"(p));
    return a;
}
#define CP_ASYNC16(dst, src) \
    asm volatile("cp.async.cg.shared.global [%0], [%1], 16;" :: "r"(dst), "l"(src) : "memory")
#define CP_COMMIT() asm volatile("cp.async.commit_group;" ::: "memory")
#define CP_WAIT(n)  asm volatile("cp.async.wait_group %0;" :: "n"(n) : "memory")

#define LDSM_X4(r0, r1, r2, r3, addr) \
    asm volatile("ldmatrix.sync.aligned.m8n8.x4.shared.b16 {%0,%1,%2,%3}, [%4];" \
                 : "=r"(r0), "=r"(r1), "=r"(r2), "=r"(r3) : "r"(addr))

#define MMA_BF16(c, a, b) \
    asm volatile("mma.sync.aligned.m16n8k16.row.col.f32.bf16.bf16.f32 " \
                 "{%0,%1,%2,%3}, {%4,%5,%6,%7}, {%8,%9}, {%0,%1,%2,%3};" \
                 : "+f"((c)[0]), "+f"((c)[1]), "+f"((c)[2]), "+f"((c)[3]) \
                 : "r"((a)[0]), "r"((a)[1]), "r"((a)[2]), "r"((a)[3]), \
                   "r"((b)[0]), "r"((b)[1]))

// ---------------- small kernels ----------------
__global__ void k_init() {
    int t = threadIdx.x;
    if (t < NEXP) { g_counts[t] = 0; g_fill[t] = 0; }
    if (t == 0) g_ticket = 0;
}

__global__ void k_router(const float* __restrict__ x,
                         const float* __restrict__ rw,
                         const float* __restrict__ rb) {
    int warp = (blockIdx.x * blockDim.x + threadIdx.x) >> 5;
    int lane = threadIdx.x & 31;
    if (warp >= NTOK) return;
    const float4* xr = (const float4*)(x + (size_t)warp * DIM);
    float acc[NEXP];
#pragma unroll
    for (int e = 0; e < NEXP; e++) acc[e] = 0.f;
#pragma unroll 4
    for (int i = lane; i < DIM / 4; i += 32) {
        float4 xv = xr[i];
#pragma unroll
        for (int e = 0; e < NEXP; e++) {
            float4 wv = ((const float4*)(rw + e * DIM))[i];
            acc[e] += xv.x * wv.x + xv.y * wv.y + xv.z * wv.z + xv.w * wv.w;
        }
    }
#pragma unroll
    for (int e = 0; e < NEXP; e++)
#pragma unroll
        for (int o = 16; o > 0; o >>= 1)
            acc[e] += __shfl_xor_sync(0xFFFFFFFFu, acc[e], o);
    if (lane == 0) {
        float best = -1e30f; int bi = 0;
#pragma unroll
        for (int e = 0; e < NEXP; e++) {
            float l = acc[e] + rb[e];
            if (l > best) { best = l; bi = e; }
        }
        float s = 0.f;
#pragma unroll
        for (int e = 0; e < NEXP; e++) s += expf(acc[e] + rb[e] - best);
        g_weight[warp] = 1.f / s;
        g_expert[warp] = bi;
        atomicAdd(&g_counts[bi], 1);
    }
}

__global__ void k_scan() {
    if (threadIdx.x == 0 && blockIdx.x == 0) {
        int off = 0, nt = 0;
        for (int e = 0; e < NEXP; e++) {
            g_offsets[e] = off;
            int c = g_counts[e];
            for (int s = 0; s < c; s += TM) g_tiles[nt++] = make_int2(e, off + s);
            off += c;
        }
        g_offsets[NEXP] = off;
        g_num_tiles = nt;
    }
}

// fused scatter + gather + fp32->bf16 hi/lo split (one block per token)
__global__ void k_scatter_prep(const float* __restrict__ x) {
    __shared__ int pos_s;
    int t = blockIdx.x;
    if (threadIdx.x == 0) {
        int e = g_expert[t];
        int pos = g_offsets[e] + atomicAdd(&g_fill[e], 1);
        g_sorted[pos] = t;
        pos_s = pos;
    }
    __syncthreads();
    int p = pos_s;
    float4 v = ((const float4*)(x + (size_t)t * DIM))[threadIdx.x];
    union { __nv_bfloat16 h[4]; uint2 u; } hi, lo;
    float f[4] = {v.x, v.y, v.z, v.w};
#pragma unroll
    for (int j = 0; j < 4; j++) {
        hi.h[j] = __float2bfloat16(f[j]);
        lo.h[j] = __float2bfloat16(f[j] - __bfloat162float(hi.h[j]));
    }
    ((uint2*)(g_xhi + (size_t)p * DIM))[threadIdx.x] = hi.u;
    ((uint2*)(g_xlo + (size_t)p * DIM))[threadIdx.x] = lo.u;
}

__global__ void k_prep_w(const float* __restrict__ ew) {
    size_t i4 = (size_t)blockIdx.x * blockDim.x + threadIdx.x;
    float4 v = ((const float4*)ew)[i4];
    union { __nv_bfloat16 h[4]; uint2 u; } hi, lo;
    float f[4] = {v.x, v.y, v.z, v.w};
#pragma unroll
    for (int j = 0; j < 4; j++) {
        hi.h[j] = __float2bfloat16(f[j]);
        lo.h[j] = __float2bfloat16(f[j] - __bfloat162float(hi.h[j]));
    }
    ((uint2*)g_whi)[i4] = hi.u;
    ((uint2*)g_wlo)[i4] = lo.u;
}

// ---------------- persistent mma.sync grouped GEMM ----------------
__global__ void __launch_bounds__(256, 2) k_gemm(const float* __restrict__ eb,
                                                 float* __restrict__ out) {
    extern __shared__ char smem[];
    uint32_t sb = smem_u32(smem);
    __shared__ int   s_job;
    __shared__ int   s_tok[TM];
    __shared__ float s_w[TM];

    int tid = threadIdx.x;
    int wid = tid >> 5;
    int lane = tid & 31;
    int warp_m = wid & 3;    // 32-row slab
    int warp_n = wid >> 2;   // 64-col slab

    // ldmatrix lane offsets (bytes within a matrix)
    uint32_t aoff = (uint32_t)((warp_m * 32 + (lane & 15)) * SROW + (lane >> 4) * 16);
    uint32_t boff = (uint32_t)((warp_n * 64 + ((lane >> 4) << 3) + (lane & 7)) * SROW
                               + ((lane >> 3) & 1) * 16);

    for (;;) {
        if (tid == 0) s_job = atomicAdd(&g_ticket, 1);
        __syncthreads();
        int job = s_job;
        int njobs = g_num_tiles * (DIM / TN);
        if (job >= njobs) return;

        int nb   = job & 7;          // DIM/TN == 8
        int tile = job >> 3;
        int2 td = g_tiles[tile];
        int e = td.x, row0 = td.y;
        int segend = g_offsets[e + 1];
        int n0 = nb * TN;

        if (tid < TM) {
            int r = row0 + tid;
            int tok = (r < segend) ? g_sorted[r] : -1;
            s_tok[tid] = tok;
            s_w[tid]   = (tok >= 0) ? g_weight[tok] : 0.f;
        }

        float c[2][8][4];
#pragma unroll
        for (int mt = 0; mt < 2; mt++)
#pragma unroll
            for (int nt = 0; nt < 8; nt++)
#pragma unroll
                for (int j = 0; j < 4; j++) c[mt][nt][j] = 0.f;

        auto issue = [&](int ch, int st) {
            int k0 = ch * KC;
            uint32_t stbase = sb + st * STAGE_BYTES;
#pragma unroll
            for (int i = 0; i < 8; i++) {
                int idx = i * 256 + tid;
                int mat = idx >> 9;
                int w   = idx & 511;
                int row = w >> 2;
                int seg = w & 3;
                uint32_t dst = stbase + mat * MAT_BYTES + row * SROW + seg * 16;
                const __nv_bfloat16* src;
                if (mat == 0)      src = g_xhi + (size_t)(row0 + row) * DIM + k0 + seg * 8;
                else if (mat == 1) src = g_xlo + (size_t)(row0 + row) * DIM + k0 + seg * 8;
                else if (mat == 2) src = g_whi + (size_t)(e * DIM + n0 + row) * DIM + k0 + seg * 8;
                else               src = g_wlo + (size_t)(e * DIM + n0 + row) * DIM + k0 + seg * 8;
                CP_ASYNC16(dst, src);
            }
            CP_COMMIT();
        };

        issue(0, 0);
        issue(1, 1);

        for (int ch = 0; ch < NCH; ch++) {
            int st = ch & 1;
            if (ch == NCH - 1) CP_WAIT(0); else CP_WAIT(1);
            __syncthreads();

            uint32_t sA = sb + st * STAGE_BYTES;
            uint32_t sB = sA + 2 * MAT_BYTES;
#pragma unroll
            for (int ks = 0; ks < 2; ks++) {
                uint32_t kb = ks * 32;           // 16 elems * 2B
                uint32_t ah[2][4], al[2][4], bh[8][2], bl[8][2];
#pragma unroll
                for (int mt = 0; mt < 2; mt++) {
                    uint32_t a = sA + mt * (16 * SROW) + aoff + kb;
                    LDSM_X4(ah[mt][0], ah[mt][1], ah[mt][2], ah[mt][3], a);
                    LDSM_X4(al[mt][0], al[mt][1], al[mt][2], al[mt][3], a + MAT_BYTES);
                }
#pragma unroll
                for (int p = 0; p < 4; p++) {
                    uint32_t b = sB + p * (16 * SROW) + boff + kb;
                    LDSM_X4(bh[p * 2][0], bh[p * 2][1], bh[p * 2 + 1][0], bh[p * 2 + 1][1], b);
                    LDSM_X4(bl[p * 2][0], bl[p * 2][1], bl[p * 2 + 1][0], bl[p * 2 + 1][1], b + MAT_BYTES);
                }
#pragma unroll
                for (int mt = 0; mt < 2; mt++)
#pragma unroll
                    for (int nt = 0; nt < 8; nt++) {
                        MMA_BF16(c[mt][nt], ah[mt], bh[nt]);
                        MMA_BF16(c[mt][nt], ah[mt], bl[nt]);
                        MMA_BF16(c[mt][nt], al[mt], bh[nt]);
                    }
            }
            __syncthreads();
            if (ch + NSTAGE < NCH) issue(ch + NSTAGE, st);
        }

        // ---------------- epilogue ----------------
        int ncol_base = n0 + warp_n * 64 + (lane & 3) * 2;
#pragma unroll
        for (int mt = 0; mt < 2; mt++) {
#pragma unroll
            for (int half = 0; half < 2; half++) {
                int rl = warp_m * 32 + mt * 16 + (lane >> 2) + half * 8;
                int tok = s_tok[rl];
                if (tok < 0) continue;
                float wt = s_w[rl];
                float* orow = out + (size_t)tok * DIM;
#pragma unroll
                for (int nt = 0; nt < 8; nt++) {
                    int nc = ncol_base + nt * 8;
                    float2 b2 = *(const float2*)(eb + (size_t)e * DIM + nc);
                    float2 r2;
                    r2.x = (c[mt][nt][half * 2 + 0] + b2.x) * wt;
                    r2.y = (c[mt][nt][half * 2 + 1] + b2.y) * wt;
                    *(float2*)(orow + nc) = r2;
                }
            }
        }
        __syncthreads();   // protect s_job / s_tok before next job
    }
}

// ---------------- launch ----------------
extern "C" void kernel_launch(void* const* d_in, const int* in_sizes, int n_in,
                              void* d_out, int out_size) {
    const float* x  = (const float*)d_in[0];
    const float* rw = (const float*)d_in[1];
    const float* rb = (const float*)d_in[2];
    const float* ew = (const float*)d_in[3];
    const float* eb = (const float*)d_in[4];
    float* out = (float*)d_out;

    cudaFuncSetAttribute(k_gemm, cudaFuncAttributeMaxDynamicSharedMemorySize, SMEM_BYTES);

    k_init<<<1, 32>>>();
    k_router<<<(NTOK * 32) / 256, 256>>>(x, rw, rb);
    k_scan<<<1, 32>>>();
    k_scatter_prep<<<NTOK, 256>>>(x);
    k_prep_w<<<(NEXP * DIM * DIM) / (256 * 4), 256>>>(ew);
    k_gemm<<<GEMM_CTAS, 256, SMEM_BYTES>>>(eb, out);
}

// round 5
// speedup vs baseline: 5.3329x; 1.3026x over previous
#include <cuda_runtime.h>
#include <cuda_bf16.h>
#include <cuda_fp16.h>
#include <math.h>
#include <stdint.h>

#define NTOK 4096
#define DIM  1024
#define NEXP 8
#define TM   128
#define TN   128
#define KC   32                      // K elems per pipeline chunk
#define NCH  (DIM / KC)              // 32
#define MAX_TILES (NTOK / TM + NEXP) // 40

// padded SMEM row: 32 fp16 data + 8 pad = 40 elems = 80 bytes
#define SROW 80
#define MAT_BYTES   (128 * SROW)         // 10240
#define STAGE_BYTES (3 * MAT_BYTES)      // 30720 (A_hi, A_lo, B)
#define NSTAGE 3
#define SMEM_BYTES  (NSTAGE * STAGE_BYTES)   // 92160

#define GEMM_CTAS (2 * 148)

// ---------------- device scratch ----------------
__device__ float g_weight[NTOK];
__device__ int   g_expert[NTOK];
__device__ int   g_counts[NEXP];
__device__ int   g_fill[NEXP];
__device__ int   g_offsets[NEXP + 1];
__device__ int   g_sorted[NTOK];
__device__ int2  g_tiles[MAX_TILES];
__device__ int   g_num_tiles;
__device__ int   g_ticket;
__device__ __half g_xhi[(NTOK + TM) * DIM];
__device__ __half g_xlo[(NTOK + TM) * DIM];
__device__ __half g_wh[NEXP * DIM * DIM];

// ---------------- PTX helpers (base compute_103 only) ----------------
__device__ __forceinline__ uint32_t smem_u32(const void* p) {
    uint32_t a;
    asm("{ .reg .u64 t; cvta.to.shared.u64 t, %1; cvt.u32.u64 %0, t; }" : "=r"(a) : "l"(p));
    return a;
}
#define CP_ASYNC16(dst, src) \
    asm volatile("cp.async.cg.shared.global [%0], [%1], 16;" :: "r"(dst), "l"(src) : "memory")
#define CP_COMMIT() asm volatile("cp.async.commit_group;" ::: "memory")
#define CP_WAIT(n)  asm volatile("cp.async.wait_group %0;" :: "n"(n) : "memory")

#define LDSM_X4(r0, r1, r2, r3, addr) \
    asm volatile("ldmatrix.sync.aligned.m8n8.x4.shared.b16 {%0,%1,%2,%3}, [%4];" \
                 : "=r"(r0), "=r"(r1), "=r"(r2), "=r"(r3) : "r"(addr))

#define MMA_F16(c, a, b) \
    asm volatile("mma.sync.aligned.m16n8k16.row.col.f32.f16.f16.f32 " \
                 "{%0,%1,%2,%3}, {%4,%5,%6,%7}, {%8,%9}, {%0,%1,%2,%3};" \
                 : "+f"((c)[0]), "+f"((c)[1]), "+f"((c)[2]), "+f"((c)[3]) \
                 : "r"((a)[0]), "r"((a)[1]), "r"((a)[2]), "r"((a)[3]), \
                   "r"((b)[0]), "r"((b)[1]))

// ---------------- small kernels ----------------
__global__ void k_init() {
    int t = threadIdx.x;
    if (t < NEXP) { g_counts[t] = 0; g_fill[t] = 0; }
    if (t == 0) g_ticket = 0;
}

__global__ void k_router(const float* __restrict__ x,
                         const float* __restrict__ rw,
                         const float* __restrict__ rb) {
    int warp = (blockIdx.x * blockDim.x + threadIdx.x) >> 5;
    int lane = threadIdx.x & 31;
    if (warp >= NTOK) return;
    const float4* xr = (const float4*)(x + (size_t)warp * DIM);
    float acc[NEXP];
#pragma unroll
    for (int e = 0; e < NEXP; e++) acc[e] = 0.f;
#pragma unroll 4
    for (int i = lane; i < DIM / 4; i += 32) {
        float4 xv = xr[i];
#pragma unroll
        for (int e = 0; e < NEXP; e++) {
            float4 wv = ((const float4*)(rw + e * DIM))[i];
            acc[e] += xv.x * wv.x + xv.y * wv.y + xv.z * wv.z + xv.w * wv.w;
        }
    }
#pragma unroll
    for (int e = 0; e < NEXP; e++)
#pragma unroll
        for (int o = 16; o > 0; o >>= 1)
            acc[e] += __shfl_xor_sync(0xFFFFFFFFu, acc[e], o);
    if (lane == 0) {
        float best = -1e30f; int bi = 0;
#pragma unroll
        for (int e = 0; e < NEXP; e++) {
            float l = acc[e] + rb[e];
            if (l > best) { best = l; bi = e; }
        }
        float s = 0.f;
#pragma unroll
        for (int e = 0; e < NEXP; e++) s += expf(acc[e] + rb[e] - best);
        g_weight[warp] = 1.f / s;
        g_expert[warp] = bi;
        atomicAdd(&g_counts[bi], 1);
    }
}

__global__ void k_scan() {
    if (threadIdx.x == 0 && blockIdx.x == 0) {
        int off = 0, nt = 0;
        for (int e = 0; e < NEXP; e++) {
            g_offsets[e] = off;
            int c = g_counts[e];
            for (int s = 0; s < c; s += TM) g_tiles[nt++] = make_int2(e, off + s);
            off += c;
        }
        g_offsets[NEXP] = off;
        g_num_tiles = nt;
    }
}

// fused scatter + gather + fp32->fp16 hi/lo split (one block per token)
__global__ void k_scatter_prep(const float* __restrict__ x) {
    __shared__ int pos_s;
    int t = blockIdx.x;
    if (threadIdx.x == 0) {
        int e = g_expert[t];
        int pos = g_offsets[e] + atomicAdd(&g_fill[e], 1);
        g_sorted[pos] = t;
        pos_s = pos;
    }
    __syncthreads();
    int p = pos_s;
    float4 v = ((const float4*)(x + (size_t)t * DIM))[threadIdx.x];
    union { __half h[4]; uint2 u; } hi, lo;
    float f[4] = {v.x, v.y, v.z, v.w};
#pragma unroll
    for (int j = 0; j < 4; j++) {
        hi.h[j] = __float2half(f[j]);
        lo.h[j] = __float2half(f[j] - __half2float(hi.h[j]));
    }
    ((uint2*)(g_xhi + (size_t)p * DIM))[threadIdx.x] = hi.u;
    ((uint2*)(g_xlo + (size_t)p * DIM))[threadIdx.x] = lo.u;
}

__global__ void k_prep_w(const float* __restrict__ ew) {
    size_t i4 = (size_t)blockIdx.x * blockDim.x + threadIdx.x;
    float4 v = ((const float4*)ew)[i4];
    union { __half h[4]; uint2 u; } h4;
    h4.h[0] = __float2half(v.x);
    h4.h[1] = __float2half(v.y);
    h4.h[2] = __float2half(v.z);
    h4.h[3] = __float2half(v.w);
    ((uint2*)g_wh)[i4] = h4.u;
}

// ---------------- persistent mma.sync grouped GEMM ----------------
__global__ void __launch_bounds__(256, 2) k_gemm(const float* __restrict__ eb,
                                                 float* __restrict__ out) {
    extern __shared__ char smem[];
    uint32_t sb = smem_u32(smem);
    __shared__ int   s_job;
    __shared__ int   s_tok[TM];
    __shared__ float s_w[TM];

    int tid = threadIdx.x;
    int wid = tid >> 5;
    int lane = tid & 31;
    int warp_m = wid & 3;    // 32-row slab
    int warp_n = wid >> 2;   // 64-col slab

    // ldmatrix lane offsets (bytes within a matrix)
    uint32_t aoff = (uint32_t)((warp_m * 32 + (lane & 15)) * SROW + (lane >> 4) * 16);
    uint32_t boff = (uint32_t)((warp_n * 64 + ((lane >> 4) << 3) + (lane & 7)) * SROW
                               + ((lane >> 3) & 1) * 16);

    for (;;) {
        if (tid == 0) s_job = atomicAdd(&g_ticket, 1);
        __syncthreads();
        int job = s_job;
        int njobs = g_num_tiles * (DIM / TN);
        if (job >= njobs) return;

        int nb   = job & 7;          // DIM/TN == 8
        int tile = job >> 3;
        int2 td = g_tiles[tile];
        int e = td.x, row0 = td.y;
        int segend = g_offsets[e + 1];
        int n0 = nb * TN;

        if (tid < TM) {
            int r = row0 + tid;
            int tok = (r < segend) ? g_sorted[r] : -1;
            s_tok[tid] = tok;
            s_w[tid]   = (tok >= 0) ? g_weight[tok] : 0.f;
        }

        float c[2][8][4];
#pragma unroll
        for (int mt = 0; mt < 2; mt++)
#pragma unroll
            for (int nt = 0; nt < 8; nt++)
#pragma unroll
                for (int j = 0; j < 4; j++) c[mt][nt][j] = 0.f;

        // 3 mats x 128 rows x 4 segs = 1536 cp.async / 256 thr = 6 each
        auto issue = [&](int ch, int st) {
            int k0 = ch * KC;
            uint32_t stbase = sb + st * STAGE_BYTES;
#pragma unroll
            for (int i = 0; i < 6; i++) {
                int idx = i * 256 + tid;
                int mat = idx >> 9;
                int w   = idx & 511;
                int row = w >> 2;
                int seg = w & 3;
                uint32_t dst = stbase + mat * MAT_BYTES + row * SROW + seg * 16;
                const __half* src;
                if (mat == 0)      src = g_xhi + (size_t)(row0 + row) * DIM + k0 + seg * 8;
                else if (mat == 1) src = g_xlo + (size_t)(row0 + row) * DIM + k0 + seg * 8;
                else               src = g_wh + (size_t)(e * DIM + n0 + row) * DIM + k0 + seg * 8;
                CP_ASYNC16(dst, src);
            }
            CP_COMMIT();
        };

        issue(0, 0); issue(1, 1); issue(2, 2);

        for (int ch = 0; ch < NCH; ch++) {
            int st = ch % NSTAGE;
            int rem = NCH - 1 - ch;
            if (rem >= 2) CP_WAIT(2);
            else if (rem == 1) CP_WAIT(1);
            else CP_WAIT(0);
            __syncthreads();

            uint32_t sA = sb + st * STAGE_BYTES;
            uint32_t sB = sA + 2 * MAT_BYTES;
#pragma unroll
            for (int ks = 0; ks < 2; ks++) {
                uint32_t kb = ks * 32;           // 16 elems * 2B
                uint32_t ah[2][4], al[2][4], b[8][2];
#pragma unroll
                for (int mt = 0; mt < 2; mt++) {
                    uint32_t a = sA + mt * (16 * SROW) + aoff + kb;
                    LDSM_X4(ah[mt][0], ah[mt][1], ah[mt][2], ah[mt][3], a);
                    LDSM_X4(al[mt][0], al[mt][1], al[mt][2], al[mt][3], a + MAT_BYTES);
                }
#pragma unroll
                for (int p = 0; p < 4; p++) {
                    uint32_t ba = sB + p * (16 * SROW) + boff + kb;
                    LDSM_X4(b[p * 2][0], b[p * 2][1], b[p * 2 + 1][0], b[p * 2 + 1][1], ba);
                }
#pragma unroll
                for (int mt = 0; mt < 2; mt++)
#pragma unroll
                    for (int nt = 0; nt < 8; nt++) {
                        MMA_F16(c[mt][nt], ah[mt], b[nt]);
                        MMA_F16(c[mt][nt], al[mt], b[nt]);
                    }
            }
            __syncthreads();
            if (ch + NSTAGE < NCH) issue(ch + NSTAGE, st);
        }

        // ---------------- epilogue ----------------
        int ncol_base = n0 + warp_n * 64 + (lane & 3) * 2;
#pragma unroll
        for (int mt = 0; mt < 2; mt++) {
#pragma unroll
            for (int half = 0; half < 2; half++) {
                int rl = warp_m * 32 + mt * 16 + (lane >> 2) + half * 8;
                int tok = s_tok[rl];
                if (tok < 0) continue;
                float wt = s_w[rl];
                float* orow = out + (size_t)tok * DIM;
#pragma unroll
                for (int nt = 0; nt < 8; nt++) {
                    int nc = ncol_base + nt * 8;
                    float2 b2 = *(const float2*)(eb + (size_t)e * DIM + nc);
                    float2 r2;
                    r2.x = (c[mt][nt][half * 2 + 0] + b2.x) * wt;
                    r2.y = (c[mt][nt][half * 2 + 1] + b2.y) * wt;
                    *(float2*)(orow + nc) = r2;
                }
            }
        }
        __syncthreads();   // protect s_job / s_tok before next job
    }
}

// ---------------- launch ----------------
extern "C" void kernel_launch(void* const* d_in, const int* in_sizes, int n_in,
                              void* d_out, int out_size) {
    const float* x  = (const float*)d_in[0];
    const float* rw = (const float*)d_in[1];
    const float* rb = (const float*)d_in[2];
    const float* ew = (const float*)d_in[3];
    const float* eb = (const float*)d_in[4];
    float* out = (float*)d_out;

    cudaFuncSetAttribute(k_gemm, cudaFuncAttributeMaxDynamicSharedMemorySize, SMEM_BYTES);

    k_init<<<1, 32>>>();
    k_router<<<(NTOK * 32) / 256, 256>>>(x, rw, rb);
    k_scan<<<1, 32>>>();
    k_scatter_prep<<<NTOK, 256>>>(x);
    k_prep_w<<<(NEXP * DIM * DIM) / (256 * 4), 256>>>(ew);
    k_gemm<<<GEMM_CTAS, 256, SMEM_BYTES>>>(eb, out);
}

// round 6
// speedup vs baseline: 5.5164x; 1.0344x over previous
#include <cuda_runtime.h>
#include <cuda_bf16.h>
#include <cuda_fp16.h>
#include <math.h>
#include <stdint.h>

#define NTOK 4096
#define DIM  1024
#define NEXP 8
#define TM   128
#define TN   128
#define KC   64                      // K elems per pipeline chunk
#define NCH  (DIM / KC)              // 16
#define MAX_TILES (NTOK / TM + NEXP) // 40

// padded SMEM row: 64 fp16 data + 8 pad = 72 elems = 144 bytes (conflict-free)
#define SROW 144
#define MAT_BYTES   (128 * SROW)         // 18432
#define STAGE_BYTES (3 * MAT_BYTES)      // 55296 (A_hi, A_lo, B)
#define NSTAGE 2
#define SMEM_BYTES  (NSTAGE * STAGE_BYTES)   // 110592

#define GEMM_CTAS (2 * 148)

// ---------------- device scratch ----------------
__device__ float g_weight[NTOK];
__device__ int   g_expert[NTOK];
__device__ int   g_counts[NEXP];
__device__ int   g_fill[NEXP];
__device__ int   g_offsets[NEXP + 1];
__device__ int   g_sorted[NTOK];
__device__ int2  g_tiles[MAX_TILES];
__device__ int   g_num_tiles;
__device__ int   g_ticket;
__device__ __half g_xhi[(NTOK + TM) * DIM];
__device__ __half g_xlo[(NTOK + TM) * DIM];
__device__ __half g_wh[NEXP * DIM * DIM];

// ---------------- PTX helpers (base compute_103 only) ----------------
__device__ __forceinline__ uint32_t smem_u32(const void* p) {
    uint32_t a;
    asm("{ .reg .u64 t; cvta.to.shared.u64 t, %1; cvt.u32.u64 %0, t; }" : "=r"(a) : "l"(p));
    return a;
}
#define CP_ASYNC16(dst, src) \
    asm volatile("cp.async.cg.shared.global [%0], [%1], 16;" :: "r"(dst), "l"(src) : "memory")
#define CP_COMMIT() asm volatile("cp.async.commit_group;" ::: "memory")
#define CP_WAIT(n)  asm volatile("cp.async.wait_group %0;" :: "n"(n) : "memory")

#define LDSM_X4(r0, r1, r2, r3, addr) \
    asm volatile("ldmatrix.sync.aligned.m8n8.x4.shared.b16 {%0,%1,%2,%3}, [%4];" \
                 : "=r"(r0), "=r"(r1), "=r"(r2), "=r"(r3) : "r"(addr))

#define MMA_F16(c, a, b) \
    asm volatile("mma.sync.aligned.m16n8k16.row.col.f32.f16.f16.f32 " \
                 "{%0,%1,%2,%3}, {%4,%5,%6,%7}, {%8,%9}, {%0,%1,%2,%3};" \
                 : "+f"((c)[0]), "+f"((c)[1]), "+f"((c)[2]), "+f"((c)[3]) \
                 : "r"((a)[0]), "r"((a)[1]), "r"((a)[2]), "r"((a)[3]), \
                   "r"((b)[0]), "r"((b)[1]))

// ---------------- small kernels ----------------
__global__ void k_init() {
    int t = threadIdx.x;
    if (t < NEXP) { g_counts[t] = 0; g_fill[t] = 0; }
    if (t == 0) g_ticket = 0;
}

// router: no global atomics (counts done in k_hist)
__global__ void k_router(const float* __restrict__ x,
                         const float* __restrict__ rw,
                         const float* __restrict__ rb) {
    int warp = (blockIdx.x * blockDim.x + threadIdx.x) >> 5;
    int lane = threadIdx.x & 31;
    if (warp >= NTOK) return;
    const float4* xr = (const float4*)(x + (size_t)warp * DIM);
    float acc[NEXP];
#pragma unroll
    for (int e = 0; e < NEXP; e++) acc[e] = 0.f;
#pragma unroll 4
    for (int i = lane; i < DIM / 4; i += 32) {
        float4 xv = xr[i];
#pragma unroll
        for (int e = 0; e < NEXP; e++) {
            float4 wv = ((const float4*)(rw + e * DIM))[i];
            acc[e] += xv.x * wv.x + xv.y * wv.y + xv.z * wv.z + xv.w * wv.w;
        }
    }
#pragma unroll
    for (int e = 0; e < NEXP; e++)
#pragma unroll
        for (int o = 16; o > 0; o >>= 1)
            acc[e] += __shfl_xor_sync(0xFFFFFFFFu, acc[e], o);
    if (lane == 0) {
        float best = -1e30f; int bi = 0;
#pragma unroll
        for (int e = 0; e < NEXP; e++) {
            float l = acc[e] + rb[e];
            if (l > best) { best = l; bi = e; }
        }
        float s = 0.f;
#pragma unroll
        for (int e = 0; e < NEXP; e++) s += expf(acc[e] + rb[e] - best);
        g_weight[warp] = 1.f / s;
        g_expert[warp] = bi;
    }
}

// histogram: block-aggregated counts (16 blocks x 256)
__global__ void k_hist() {
    __shared__ int h[NEXP];
    if (threadIdx.x < NEXP) h[threadIdx.x] = 0;
    __syncthreads();
    int t = blockIdx.x * blockDim.x + threadIdx.x;
    atomicAdd(&h[g_expert[t]], 1);
    __syncthreads();
    if (threadIdx.x < NEXP) atomicAdd(&g_counts[threadIdx.x], h[threadIdx.x]);
}

__global__ void k_scan() {
    if (threadIdx.x == 0 && blockIdx.x == 0) {
        int off = 0, nt = 0;
        for (int e = 0; e < NEXP; e++) {
            g_offsets[e] = off;
            int c = g_counts[e];
            for (int s = 0; s < c; s += TM) g_tiles[nt++] = make_int2(e, off + s);
            off += c;
        }
        g_offsets[NEXP] = off;
        g_num_tiles = nt;
    }
}

// position assignment via ballot aggregation (16 blocks x 256; 8 atomics/block)
__global__ void k_pos() {
    __shared__ int warp_cnt[8][NEXP];
    __shared__ int warp_base[8][NEXP];
    int t = blockIdx.x * blockDim.x + threadIdx.x;
    int e = g_expert[t];
    int lane = threadIdx.x & 31, w = threadIdx.x >> 5;
    int lane_rank = 0;
#pragma unroll
    for (int ee = 0; ee < NEXP; ee++) {
        unsigned m = __ballot_sync(0xFFFFFFFFu, e == ee);
        if (e == ee) lane_rank = __popc(m & ((1u << lane) - 1));
        if (lane == 0) warp_cnt[w][ee] = __popc(m);
    }
    __syncthreads();
    if (threadIdx.x < NEXP) {
        int ee = threadIdx.x;
        int sum = 0, pre[8];
#pragma unroll
        for (int ww = 0; ww < 8; ww++) { pre[ww] = sum; sum += warp_cnt[ww][ee]; }
        int base = atomicAdd(&g_fill[ee], sum);
#pragma unroll
        for (int ww = 0; ww < 8; ww++) warp_base[ww][ee] = base + pre[ww];
    }
    __syncthreads();
    int pos = g_offsets[e] + warp_base[w][e] + lane_rank;
    g_sorted[pos] = t;
}

// destination-indexed gather + fp32->fp16 hi/lo split (atomic-free streaming)
__global__ void k_prep_x(const float* __restrict__ x) {
    int p = blockIdx.x;
    int tok = g_sorted[p];
    float4 v = ((const float4*)(x + (size_t)tok * DIM))[threadIdx.x];
    union { __half h[4]; uint2 u; } hi, lo;
    float f[4] = {v.x, v.y, v.z, v.w};
#pragma unroll
    for (int j = 0; j < 4; j++) {
        hi.h[j] = __float2half(f[j]);
        lo.h[j] = __float2half(f[j] - __half2float(hi.h[j]));
    }
    ((uint2*)(g_xhi + (size_t)p * DIM))[threadIdx.x] = hi.u;
    ((uint2*)(g_xlo + (size_t)p * DIM))[threadIdx.x] = lo.u;
}

__global__ void k_prep_w(const float* __restrict__ ew) {
    size_t i4 = (size_t)blockIdx.x * blockDim.x + threadIdx.x;
    float4 v = ((const float4*)ew)[i4];
    union { __half h[4]; uint2 u; } h4;
    h4.h[0] = __float2half(v.x);
    h4.h[1] = __float2half(v.y);
    h4.h[2] = __float2half(v.z);
    h4.h[3] = __float2half(v.w);
    ((uint2*)g_wh)[i4] = h4.u;
}

// ---------------- persistent mma.sync grouped GEMM ----------------
__global__ void __launch_bounds__(256, 2) k_gemm(const float* __restrict__ eb,
                                                 float* __restrict__ out) {
    extern __shared__ char smem[];
    uint32_t sb = smem_u32(smem);
    __shared__ int   s_job;
    __shared__ int   s_tok[TM];
    __shared__ float s_w[TM];

    int tid = threadIdx.x;
    int wid = tid >> 5;
    int lane = tid & 31;
    int warp_m = wid & 3;    // 32-row slab
    int warp_n = wid >> 2;   // 64-col slab

    uint32_t aoff = (uint32_t)((warp_m * 32 + (lane & 15)) * SROW + (lane >> 4) * 16);
    uint32_t boff = (uint32_t)((warp_n * 64 + ((lane >> 4) << 3) + (lane & 7)) * SROW
                               + ((lane >> 3) & 1) * 16);

    for (;;) {
        if (tid == 0) s_job = atomicAdd(&g_ticket, 1);
        __syncthreads();
        int job = s_job;
        int njobs = g_num_tiles * (DIM / TN);
        if (job >= njobs) return;

        int nb   = job & 7;          // DIM/TN == 8
        int tile = job >> 3;
        int2 td = g_tiles[tile];
        int e = td.x, row0 = td.y;
        int segend = g_offsets[e + 1];
        int n0 = nb * TN;

        if (tid < TM) {
            int r = row0 + tid;
            int tok = (r < segend) ? g_sorted[r] : -1;
            s_tok[tid] = tok;
            s_w[tid]   = (tok >= 0) ? g_weight[tok] : 0.f;
        }

        float c[2][8][4];
#pragma unroll
        for (int mt = 0; mt < 2; mt++)
#pragma unroll
            for (int nt = 0; nt < 8; nt++)
#pragma unroll
                for (int j = 0; j < 4; j++) c[mt][nt][j] = 0.f;

        // 3 mats x 128 rows x 8 segs = 3072 cp.async / 256 thr = 12 each
        auto issue = [&](int ch, int st) {
            int k0 = ch * KC;
            uint32_t stbase = sb + st * STAGE_BYTES;
#pragma unroll
            for (int i = 0; i < 12; i++) {
                int idx = i * 256 + tid;
                int mat = idx >> 10;
                int w   = idx & 1023;
                int row = w >> 3;
                int seg = w & 7;
                uint32_t dst = stbase + mat * MAT_BYTES + row * SROW + seg * 16;
                const __half* src;
                if (mat == 0)      src = g_xhi + (size_t)(row0 + row) * DIM + k0 + seg * 8;
                else if (mat == 1) src = g_xlo + (size_t)(row0 + row) * DIM + k0 + seg * 8;
                else               src = g_wh + (size_t)(e * DIM + n0 + row) * DIM + k0 + seg * 8;
                CP_ASYNC16(dst, src);
            }
            CP_COMMIT();
        };

        issue(0, 0);
        issue(1, 1);

        for (int ch = 0; ch < NCH; ch++) {
            int st = ch & 1;
            if (ch == NCH - 1) CP_WAIT(0); else CP_WAIT(1);
            __syncthreads();

            uint32_t sA = sb + st * STAGE_BYTES;
            uint32_t sB = sA + 2 * MAT_BYTES;
#pragma unroll
            for (int ks = 0; ks < 4; ks++) {
                uint32_t kb = ks * 32;           // 16 elems * 2B
                uint32_t ah[2][4], al[2][4], b[8][2];
#pragma unroll
                for (int mt = 0; mt < 2; mt++) {
                    uint32_t a = sA + mt * (16 * SROW) + aoff + kb;
                    LDSM_X4(ah[mt][0], ah[mt][1], ah[mt][2], ah[mt][3], a);
                    LDSM_X4(al[mt][0], al[mt][1], al[mt][2], al[mt][3], a + MAT_BYTES);
                }
#pragma unroll
                for (int p = 0; p < 4; p++) {
                    uint32_t ba = sB + p * (16 * SROW) + boff + kb;
                    LDSM_X4(b[p * 2][0], b[p * 2][1], b[p * 2 + 1][0], b[p * 2 + 1][1], ba);
                }
#pragma unroll
                for (int mt = 0; mt < 2; mt++)
#pragma unroll
                    for (int nt = 0; nt < 8; nt++) {
                        MMA_F16(c[mt][nt], ah[mt], b[nt]);
                        MMA_F16(c[mt][nt], al[mt], b[nt]);
                    }
            }
            __syncthreads();
            if (ch + NSTAGE < NCH) issue(ch + NSTAGE, st);
        }

        // ---------------- epilogue ----------------
        int ncol_base = n0 + warp_n * 64 + (lane & 3) * 2;
#pragma unroll
        for (int mt = 0; mt < 2; mt++) {
#pragma unroll
            for (int half = 0; half < 2; half++) {
                int rl = warp_m * 32 + mt * 16 + (lane >> 2) + half * 8;
                int tok = s_tok[rl];
                if (tok < 0) continue;
                float wt = s_w[rl];
                float* orow = out + (size_t)tok * DIM;
#pragma unroll
                for (int nt = 0; nt < 8; nt++) {
                    int nc = ncol_base + nt * 8;
                    float2 b2 = *(const float2*)(eb + (size_t)e * DIM + nc);
                    float2 r2;
                    r2.x = (c[mt][nt][half * 2 + 0] + b2.x) * wt;
                    r2.y = (c[mt][nt][half * 2 + 1] + b2.y) * wt;
                    *(float2*)(orow + nc) = r2;
                }
            }
        }
        __syncthreads();   // protect s_job / s_tok before next job
    }
}

// ---------------- launch ----------------
extern "C" void kernel_launch(void* const* d_in, const int* in_sizes, int n_in,
                              void* d_out, int out_size) {
    const float* x  = (const float*)d_in[0];
    const float* rw = (const float*)d_in[1];
    const float* rb = (const float*)d_in[2];
    const float* ew = (const float*)d_in[3];
    const float* eb = (const float*)d_in[4];
    float* out = (float*)d_out;

    cudaFuncSetAttribute(k_gemm, cudaFuncAttributeMaxDynamicSharedMemorySize, SMEM_BYTES);

    k_init<<<1, 32>>>();
    k_router<<<(NTOK * 32) / 256, 256>>>(x, rw, rb);
    k_hist<<<NTOK / 256, 256>>>();
    k_scan<<<1, 32>>>();
    k_pos<<<NTOK / 256, 256>>>();
    k_prep_x<<<NTOK, 256>>>(x);
    k_prep_w<<<(NEXP * DIM * DIM) / (256 * 4), 256>>>(ew);
    k_gemm<<<GEMM_CTAS, 256, SMEM_BYTES>>>(eb, out);
}

// round 7
// speedup vs baseline: 7.5381x; 1.3665x over previous
#include <cuda_runtime.h>
#include <cuda_bf16.h>
#include <cuda_fp16.h>
#include <math.h>
#include <stdint.h>

#define NTOK 4096
#define DIM  1024
#define NEXP 8
#define TM   128
#define TN   128
#define KC   64                      // K elems per pipeline chunk
#define NCH  (DIM / KC)              // 16
#define MAX_TILES (NTOK / TM + NEXP) // 40

// padded SMEM row: 64 fp16 data + 8 pad = 72 elems = 144 bytes (conflict-free)
#define SROW 144
#define MAT_BYTES   (128 * SROW)         // 18432
#define STAGE_BYTES (2 * MAT_BYTES)      // 36864 (A, B)
#define NSTAGE 3
#define SMEM_BYTES  (NSTAGE * STAGE_BYTES)   // 110592

#define GEMM_CTAS (2 * 148)

// ---------------- device scratch ----------------
__device__ float g_weight[NTOK];
__device__ int   g_expert[NTOK];
__device__ int   g_fill[NEXP];
__device__ int   g_offsets[NEXP + 1];
__device__ int   g_sorted[NTOK];
__device__ int2  g_tiles[MAX_TILES];
__device__ int   g_num_tiles;
__device__ int   g_ticket;
__device__ __half g_xh[(NTOK + TM) * DIM];
__device__ __half g_wh[NEXP * DIM * DIM];

// ---------------- PTX helpers (base compute_103 only) ----------------
__device__ __forceinline__ uint32_t smem_u32(const void* p) {
    uint32_t a;
    asm("{ .reg .u64 t; cvta.to.shared.u64 t, %1; cvt.u32.u64 %0, t; }" : "=r"(a) : "l"(p));
    return a;
}
#define CP_ASYNC16(dst, src) \
    asm volatile("cp.async.cg.shared.global [%0], [%1], 16;" :: "r"(dst), "l"(src) : "memory")
#define CP_COMMIT() asm volatile("cp.async.commit_group;" ::: "memory")
#define CP_WAIT(n)  asm volatile("cp.async.wait_group %0;" :: "n"(n) : "memory")

#define LDSM_X4(r0, r1, r2, r3, addr) \
    asm volatile("ldmatrix.sync.aligned.m8n8.x4.shared.b16 {%0,%1,%2,%3}, [%4];" \
                 : "=r"(r0), "=r"(r1), "=r"(r2), "=r"(r3) : "r"(addr))

#define MMA_F16(c, a, b) \
    asm volatile("mma.sync.aligned.m16n8k16.row.col.f32.f16.f16.f32 " \
                 "{%0,%1,%2,%3}, {%4,%5,%6,%7}, {%8,%9}, {%0,%1,%2,%3};" \
                 : "+f"((c)[0]), "+f"((c)[1]), "+f"((c)[2]), "+f"((c)[3]) \
                 : "r"((a)[0]), "r"((a)[1]), "r"((a)[2]), "r"((a)[3]), \
                   "r"((b)[0]), "r"((b)[1]))

// ---------------- small kernels ----------------
// router: expert + weight per token (no global atomics)
__global__ void k_router(const float* __restrict__ x,
                         const float* __restrict__ rw,
                         const float* __restrict__ rb) {
    int warp = (blockIdx.x * blockDim.x + threadIdx.x) >> 5;
    int lane = threadIdx.x & 31;
    if (warp >= NTOK) return;
    const float4* xr = (const float4*)(x + (size_t)warp * DIM);
    float acc[NEXP];
#pragma unroll
    for (int e = 0; e < NEXP; e++) acc[e] = 0.f;
#pragma unroll 4
    for (int i = lane; i < DIM / 4; i += 32) {
        float4 xv = xr[i];
#pragma unroll
        for (int e = 0; e < NEXP; e++) {
            float4 wv = ((const float4*)(rw + e * DIM))[i];
            acc[e] += xv.x * wv.x + xv.y * wv.y + xv.z * wv.z + xv.w * wv.w;
        }
    }
#pragma unroll
    for (int e = 0; e < NEXP; e++)
#pragma unroll
        for (int o = 16; o > 0; o >>= 1)
            acc[e] += __shfl_xor_sync(0xFFFFFFFFu, acc[e], o);
    if (lane == 0) {
        float best = -1e30f; int bi = 0;
#pragma unroll
        for (int e = 0; e < NEXP; e++) {
            float l = acc[e] + rb[e];
            if (l > best) { best = l; bi = e; }
        }
        float s = 0.f;
#pragma unroll
        for (int e = 0; e < NEXP; e++) s += expf(acc[e] + rb[e] - best);
        g_weight[warp] = 1.f / s;
        g_expert[warp] = bi;
    }
}

// fused init + histogram + scan + tile list (single block, 1024 threads)
__global__ void k_histscan() {
    __shared__ int h[NEXP];
    int tid = threadIdx.x;
    if (tid < NEXP) { h[tid] = 0; g_fill[tid] = 0; }
    if (tid == 0) g_ticket = 0;
    __syncthreads();
#pragma unroll
    for (int i = 0; i < NTOK / 1024; i++)
        atomicAdd(&h[g_expert[tid + i * 1024]], 1);
    __syncthreads();
    if (tid == 0) {
        int off = 0, nt = 0;
        for (int e = 0; e < NEXP; e++) {
            g_offsets[e] = off;
            int c = h[e];
            for (int s = 0; s < c; s += TM) g_tiles[nt++] = make_int2(e, off + s);
            off += c;
        }
        g_offsets[NEXP] = off;
        g_num_tiles = nt;
    }
}

// position assignment via ballot aggregation (16 blocks x 256; 8 atomics/block)
__global__ void k_pos() {
    __shared__ int warp_cnt[8][NEXP];
    __shared__ int warp_base[8][NEXP];
    int t = blockIdx.x * blockDim.x + threadIdx.x;
    int e = g_expert[t];
    int lane = threadIdx.x & 31, w = threadIdx.x >> 5;
    int lane_rank = 0;
#pragma unroll
    for (int ee = 0; ee < NEXP; ee++) {
        unsigned m = __ballot_sync(0xFFFFFFFFu, e == ee);
        if (e == ee) lane_rank = __popc(m & ((1u << lane) - 1));
        if (lane == 0) warp_cnt[w][ee] = __popc(m);
    }
    __syncthreads();
    if (threadIdx.x < NEXP) {
        int ee = threadIdx.x;
        int sum = 0, pre[8];
#pragma unroll
        for (int ww = 0; ww < 8; ww++) { pre[ww] = sum; sum += warp_cnt[ww][ee]; }
        int base = atomicAdd(&g_fill[ee], sum);
#pragma unroll
        for (int ww = 0; ww < 8; ww++) warp_base[ww][ee] = base + pre[ww];
    }
    __syncthreads();
    int pos = g_offsets[e] + warp_base[w][e] + lane_rank;
    g_sorted[pos] = t;
}

// destination-indexed gather + fp32->fp16 (atomic-free streaming)
__global__ void k_prep_x(const float* __restrict__ x) {
    int p = blockIdx.x;
    int tok = g_sorted[p];
    float4 v = ((const float4*)(x + (size_t)tok * DIM))[threadIdx.x];
    union { __half h[4]; uint2 u; } hv;
    hv.h[0] = __float2half(v.x);
    hv.h[1] = __float2half(v.y);
    hv.h[2] = __float2half(v.z);
    hv.h[3] = __float2half(v.w);
    ((uint2*)(g_xh + (size_t)p * DIM))[threadIdx.x] = hv.u;
}

__global__ void k_prep_w(const float* __restrict__ ew) {
    size_t i4 = (size_t)blockIdx.x * blockDim.x + threadIdx.x;
    float4 v = ((const float4*)ew)[i4];
    union { __half h[4]; uint2 u; } h4;
    h4.h[0] = __float2half(v.x);
    h4.h[1] = __float2half(v.y);
    h4.h[2] = __float2half(v.z);
    h4.h[3] = __float2half(v.w);
    ((uint2*)g_wh)[i4] = h4.u;
}

// ---------------- persistent mma.sync grouped GEMM (1-term fp16) ----------------
__global__ void __launch_bounds__(256, 2) k_gemm(const float* __restrict__ eb,
                                                 float* __restrict__ out) {
    extern __shared__ char smem[];
    uint32_t sb = smem_u32(smem);
    __shared__ int   s_job;
    __shared__ int   s_tok[TM];
    __shared__ float s_w[TM];

    int tid = threadIdx.x;
    int wid = tid >> 5;
    int lane = tid & 31;
    int warp_m = wid & 3;    // 32-row slab
    int warp_n = wid >> 2;   // 64-col slab

    uint32_t aoff = (uint32_t)((warp_m * 32 + (lane & 15)) * SROW + (lane >> 4) * 16);
    uint32_t boff = (uint32_t)((warp_n * 64 + ((lane >> 4) << 3) + (lane & 7)) * SROW
                               + ((lane >> 3) & 1) * 16);

    for (;;) {
        if (tid == 0) s_job = atomicAdd(&g_ticket, 1);
        __syncthreads();
        int job = s_job;
        int njobs = g_num_tiles * (DIM / TN);
        if (job >= njobs) return;

        int nb   = job & 7;          // DIM/TN == 8
        int tile = job >> 3;
        int2 td = g_tiles[tile];
        int e = td.x, row0 = td.y;
        int segend = g_offsets[e + 1];
        int n0 = nb * TN;

        if (tid < TM) {
            int r = row0 + tid;
            int tok = (r < segend) ? g_sorted[r] : -1;
            s_tok[tid] = tok;
            s_w[tid]   = (tok >= 0) ? g_weight[tok] : 0.f;
        }

        float c[2][8][4];
#pragma unroll
        for (int mt = 0; mt < 2; mt++)
#pragma unroll
            for (int nt = 0; nt < 8; nt++)
#pragma unroll
                for (int j = 0; j < 4; j++) c[mt][nt][j] = 0.f;

        // 2 mats x 128 rows x 8 segs = 2048 cp.async / 256 thr = 8 each
        auto issue = [&](int ch, int st) {
            int k0 = ch * KC;
            uint32_t stbase = sb + st * STAGE_BYTES;
#pragma unroll
            for (int i = 0; i < 8; i++) {
                int idx = i * 256 + tid;
                int mat = idx >> 10;
                int w   = idx & 1023;
                int row = w >> 3;
                int seg = w & 7;
                uint32_t dst = stbase + mat * MAT_BYTES + row * SROW + seg * 16;
                const __half* src;
                if (mat == 0) src = g_xh + (size_t)(row0 + row) * DIM + k0 + seg * 8;
                else          src = g_wh + (size_t)(e * DIM + n0 + row) * DIM + k0 + seg * 8;
                CP_ASYNC16(dst, src);
            }
            CP_COMMIT();
        };

        issue(0, 0); issue(1, 1); issue(2, 2);

        for (int ch = 0; ch < NCH; ch++) {
            int st = ch % NSTAGE;
            int rem = NCH - 1 - ch;
            if (rem >= 2) CP_WAIT(2);
            else if (rem == 1) CP_WAIT(1);
            else CP_WAIT(0);
            __syncthreads();

            uint32_t sA = sb + st * STAGE_BYTES;
            uint32_t sB = sA + MAT_BYTES;
#pragma unroll
            for (int ks = 0; ks < 4; ks++) {
                uint32_t kb = ks * 32;           // 16 elems * 2B
                uint32_t a[2][4], b[8][2];
#pragma unroll
                for (int mt = 0; mt < 2; mt++) {
                    uint32_t aa = sA + mt * (16 * SROW) + aoff + kb;
                    LDSM_X4(a[mt][0], a[mt][1], a[mt][2], a[mt][3], aa);
                }
#pragma unroll
                for (int p = 0; p < 4; p++) {
                    uint32_t ba = sB + p * (16 * SROW) + boff + kb;
                    LDSM_X4(b[p * 2][0], b[p * 2][1], b[p * 2 + 1][0], b[p * 2 + 1][1], ba);
                }
#pragma unroll
                for (int mt = 0; mt < 2; mt++)
#pragma unroll
                    for (int nt = 0; nt < 8; nt++)
                        MMA_F16(c[mt][nt], a[mt], b[nt]);
            }
            __syncthreads();
            if (ch + NSTAGE < NCH) issue(ch + NSTAGE, st);
        }

        // ---------------- epilogue ----------------
        int ncol_base = n0 + warp_n * 64 + (lane & 3) * 2;
#pragma unroll
        for (int mt = 0; mt < 2; mt++) {
#pragma unroll
            for (int half = 0; half < 2; half++) {
                int rl = warp_m * 32 + mt * 16 + (lane >> 2) + half * 8;
                int tok = s_tok[rl];
                if (tok < 0) continue;
                float wt = s_w[rl];
                float* orow = out + (size_t)tok * DIM;
#pragma unroll
                for (int nt = 0; nt < 8; nt++) {
                    int nc = ncol_base + nt * 8;
                    float2 b2 = *(const float2*)(eb + (size_t)e * DIM + nc);
                    float2 r2;
                    r2.x = (c[mt][nt][half * 2 + 0] + b2.x) * wt;
                    r2.y = (c[mt][nt][half * 2 + 1] + b2.y) * wt;
                    *(float2*)(orow + nc) = r2;
                }
            }
        }
        __syncthreads();   // protect s_job / s_tok before next job
    }
}

// ---------------- launch ----------------
extern "C" void kernel_launch(void* const* d_in, const int* in_sizes, int n_in,
                              void* d_out, int out_size) {
    const float* x  = (const float*)d_in[0];
    const float* rw = (const float*)d_in[1];
    const float* rb = (const float*)d_in[2];
    const float* ew = (const float*)d_in[3];
    const float* eb = (const float*)d_in[4];
    float* out = (float*)d_out;

    cudaFuncSetAttribute(k_gemm, cudaFuncAttributeMaxDynamicSharedMemorySize, SMEM_BYTES);

    k_router<<<(NTOK * 32) / 256, 256>>>(x, rw, rb);
    k_histscan<<<1, 1024>>>();
    k_pos<<<NTOK / 256, 256>>>();
    k_prep_x<<<NTOK, 256>>>(x);
    k_prep_w<<<(NEXP * DIM * DIM) / (256 * 4), 256>>>(ew);
    k_gemm<<<GEMM_CTAS, 256, SMEM_BYTES>>>(eb, out);
}